// round 2
// baseline (speedup 1.0000x reference)
#include <cuda_runtime.h>
#include <math.h>

#define N_TOKENS 16384
#define DIM      4096
#define NEXP     64
#define CAPACITY 640

// ---------------- static device scratch (no runtime allocation) ----------------
__device__ float g_logits[N_TOKENS * NEXP];   // 4 MB
__device__ float g_prob[N_TOKENS * 2];
__device__ int   g_idx[N_TOKENS * 2];
__device__ int   g_cnt[NEXP];

// ---------------- kernel 0: reset per-expert counters (determinism across graph replays)
__global__ void zero_counts_kernel() {
    int i = threadIdx.x;
    if (i < NEXP) g_cnt[i] = 0;
}

// ---------------- kernel 1: logits = x @ W^T  (fp32 SGEMM, smem tiled) ----------------
// Block: 64 tokens x 64 experts, BK=32. 128 threads, 8x4 microtile per thread.
__global__ void __launch_bounds__(128) gemm_kernel(const float* __restrict__ x,
                                                   const float* __restrict__ W) {
    __shared__ float xs[32][68];   // [k][token], padded
    __shared__ float ws[32][64];   // [k][expert]

    const int tid  = threadIdx.x;
    const int tx   = tid & 15;     // expert group of 4 -> experts tx*4..tx*4+3
    const int ty   = tid >> 4;     // token group of 8  -> tokens  ty*8..ty*8+7
    const int tok0 = blockIdx.x * 64;

    float acc[8][4];
#pragma unroll
    for (int i = 0; i < 8; i++)
#pragma unroll
        for (int j = 0; j < 4; j++) acc[i][j] = 0.0f;

    for (int k0 = 0; k0 < DIM; k0 += 32) {
        // Load x tile: 64 rows x 32 cols = 512 float4 (8 per row). 4 float4 per thread.
#pragma unroll
        for (int i = 0; i < 4; i++) {
            int f4   = i * 128 + tid;       // 0..511
            int row  = f4 >> 3;             // 0..63
            int col4 = f4 & 7;              // 0..7
            float4 v = *(const float4*)(x + (size_t)(tok0 + row) * DIM + k0 + col4 * 4);
            xs[col4 * 4 + 0][row] = v.x;
            xs[col4 * 4 + 1][row] = v.y;
            xs[col4 * 4 + 2][row] = v.z;
            xs[col4 * 4 + 3][row] = v.w;
        }
        // Load W tile: 64 experts x 32 cols, same mapping.
#pragma unroll
        for (int i = 0; i < 4; i++) {
            int f4   = i * 128 + tid;
            int row  = f4 >> 3;
            int col4 = f4 & 7;
            float4 v = *(const float4*)(W + (size_t)row * DIM + k0 + col4 * 4);
            ws[col4 * 4 + 0][row] = v.x;
            ws[col4 * 4 + 1][row] = v.y;
            ws[col4 * 4 + 2][row] = v.z;
            ws[col4 * 4 + 3][row] = v.w;
        }
        __syncthreads();

#pragma unroll
        for (int k = 0; k < 32; k++) {
            float4 a0 = *(const float4*)&xs[k][ty * 8];
            float4 a1 = *(const float4*)&xs[k][ty * 8 + 4];
            float4 wv = *(const float4*)&ws[k][tx * 4];
            float xr[8] = {a0.x, a0.y, a0.z, a0.w, a1.x, a1.y, a1.z, a1.w};
            float wr[4] = {wv.x, wv.y, wv.z, wv.w};
#pragma unroll
            for (int i = 0; i < 8; i++)
#pragma unroll
                for (int j = 0; j < 4; j++)
                    acc[i][j] = fmaf(xr[i], wr[j], acc[i][j]);
        }
        __syncthreads();
    }

#pragma unroll
    for (int i = 0; i < 8; i++) {
        int t = tok0 + ty * 8 + i;
        *(float4*)&g_logits[(size_t)t * NEXP + tx * 4] =
            make_float4(acc[i][0], acc[i][1], acc[i][2], acc[i][3]);
    }
}

// ---------------- kernel 2: per-token top-2 + softmax + per-expert counts ----------------
__global__ void route_kernel() {
    int t = blockIdx.x * blockDim.x + threadIdx.x;
    if (t >= N_TOKENS) return;
    const float* lg = g_logits + (size_t)t * NEXP;

    float b1 = -INFINITY, b2 = -INFINITY;
    int   i1 = 0, i2 = 0;
#pragma unroll 8
    for (int e = 0; e < NEXP; e++) {
        float v = lg[e];
        if (v > b1) { b2 = b1; i2 = i1; b1 = v; i1 = e; }
        else if (v > b2) { b2 = v; i2 = e; }
    }
    // softmax over the two selected scores (max-subtracted, matches jax semantics)
    float e2    = expf(b2 - b1);
    float denom = 1.0f + e2;
    g_prob[2 * t]     = 1.0f / denom;
    g_prob[2 * t + 1] = e2 / denom;
    g_idx[2 * t]      = i1;
    g_idx[2 * t + 1]  = i2;
    atomicAdd(&g_cnt[i1], 1);
    atomicAdd(&g_cnt[i2], 1);
}

// ---------------- kernel 3: capacity enforcement + output assembly ----------------
// Output layout (float32): [ final_probs 32768 | final_indices 32768 | counts 64 ]
__global__ void finalize_kernel(float* __restrict__ out, int out_size) {
    int i = blockIdx.x * blockDim.x + threadIdx.x;
    const int NPAIR = 2 * N_TOKENS;
    if (i < NPAIR) {
        int t = i >> 1;
        int e = g_idx[i];
        float p = g_prob[i];
        bool drop = false;
        if (g_cnt[e] > CAPACITY) {
            // exact rank of this (token,expert) gate in expert e's column:
            // strictly-greater gates rank above; equal gates with smaller token id rank above
            int rank = 0;
            for (int j = 0; j < NPAIR; j++) {
                if (g_idx[j] == e) {
                    float q = g_prob[j];
                    if (q > p || (q == p && (j >> 1) < t)) rank++;
                }
            }
            drop = (rank >= CAPACITY);
        }
        out[i] = drop ? 0.0f : p;
        if (out_size >= 2 * NPAIR)
            out[NPAIR + i] = drop ? 2147483648.0f /* float(INT32_MAX) */ : (float)e;
    } else if (i < NPAIR + NEXP) {
        int e = i - NPAIR;
        if (out_size >= 2 * NPAIR + NEXP)
            out[2 * NPAIR + e] = (float)g_cnt[e];
    }
}

// ---------------- launch ----------------
extern "C" void kernel_launch(void* const* d_in, const int* in_sizes, int n_in,
                              void* d_out, int out_size) {
    const float* x = (const float*)d_in[0];
    const float* W = (const float*)d_in[1];
    if (n_in >= 2 && in_sizes[0] < in_sizes[1]) {  // defensive: ensure x is the big tensor
        const float* tmp = x; x = W; W = tmp;
    }
    float* out = (float*)d_out;

    zero_counts_kernel<<<1, 64>>>();
    gemm_kernel<<<N_TOKENS / 64, 128>>>(x, W);
    route_kernel<<<(N_TOKENS + 255) / 256, 256>>>();
    int nfin = 2 * N_TOKENS + NEXP;
    finalize_kernel<<<(nfin + 255) / 256, 256>>>(out, out_size);
}

// round 4
// speedup vs baseline: 1.4551x; 1.4551x over previous
#include <cuda_runtime.h>
#include <math.h>
#include <stdint.h>

#define N_TOKENS 16384
#define DIM      4096
#define NEXP     64
#define CAPACITY 640

#define BM   128
#define BK   32
#define NKIT (DIM / BK)     // 128 k-iterations
#define NTHR 256
#define STAGE_F 6144        // floats per stage: A 4096 (16KB) + B 2048 (8KB)

__device__ float g_prob[N_TOKENS * 2];
__device__ int   g_idx [N_TOKENS * 2];
__device__ int   g_cnt [NEXP];

__global__ void zero_counts_kernel() {
    if (threadIdx.x < NEXP) g_cnt[threadIdx.x] = 0;
}

// fp32 -> tf32 (round to nearest), result is a b32 register holding the tf32 pattern
__device__ __forceinline__ uint32_t f2tf(float a) {
    uint32_t r; asm("cvt.rna.tf32.f32 %0, %1;" : "=r"(r) : "f"(a)); return r;
}

// D += A * B  (m16n8k8 tf32, fp32 accumulate)
__device__ __forceinline__ void mma8(float* d, const uint32_t* a, const uint32_t* b) {
    asm volatile("mma.sync.aligned.m16n8k8.row.col.f32.tf32.tf32.f32 "
        "{%0,%1,%2,%3}, {%4,%5,%6,%7}, {%8,%9}, {%0,%1,%2,%3};"
        : "+f"(d[0]), "+f"(d[1]), "+f"(d[2]), "+f"(d[3])
        : "r"(a[0]), "r"(a[1]), "r"(a[2]), "r"(a[3]), "r"(b[0]), "r"(b[1]));
}

// ---------------- fused 3xTF32 GEMM (mma.sync) + top-2 routing ----------------
// smem stores A/B in *fragment layout*:
//   A: [kstep 0..3][mtile 0..7][lane 0..31] float4 = regs (a0,a1,a2,a3)
//   B: [kstep 0..3][ntile 0..7][lane 0..31] float2 = regs (b0,b1)
// so fragment loads are one LDS.128 / LDS.64, conflict-free.
__global__ void __launch_bounds__(NTHR, 1)
gemm_route_kernel(const float* __restrict__ x, const float* __restrict__ Wm) {
    __shared__ __align__(16) float sf[2 * STAGE_F];   // 48 KB, double buffered

    const int tid  = threadIdx.x;
    const int lane = tid & 31;
    const int wid  = tid >> 5;
    const int wm   = wid >> 1;      // 0..3 -> rows wm*32..+31
    const int wn   = wid & 1;       // 0..1 -> cols wn*32..+31
    const int tok0 = blockIdx.x * BM;

    float acc[2][4][4];             // [mtile][ntile][c0..c3]
#pragma unroll
    for (int m = 0; m < 2; m++)
#pragma unroll
        for (int n = 0; n < 4; n++)
#pragma unroll
            for (int q = 0; q < 4; q++) acc[m][n][q] = 0.0f;

    float4 av[4], bv[2];            // staged global data for the next tile

    auto LDGT = [&](int i) {
        const float* xp = x + (size_t)tok0 * DIM + i * BK;
#pragma unroll
        for (int j = 0; j < 4; j++) {               // A: 128 rows x 8 float4
            int f4 = tid + j * NTHR, row = f4 >> 3, k4 = f4 & 7;
            av[j] = *(const float4*)(xp + (size_t)row * DIM + k4 * 4);
        }
        const float* wp = Wm + i * BK;
#pragma unroll
        for (int j = 0; j < 2; j++) {               // B: 64 rows x 8 float4
            int f4 = tid + j * NTHR, e = f4 >> 3, k4 = f4 & 7;
            bv[j] = *(const float4*)(wp + (size_t)e * DIM + k4 * 4);
        }
    };

    auto STST = [&](int s) {
        float* base = sf + s * STAGE_F;
#pragma unroll
        for (int j = 0; j < 4; j++) {               // scatter A into fragment layout
            int f4 = tid + j * NTHR, row = f4 >> 3, k4 = f4 & 7;
            int mt = row >> 4, r15 = row & 15, rbit = r15 >> 3, r8 = r15 & 7;
            int kstep = k4 >> 1, khalf = k4 & 1;
            float v[4] = {av[j].x, av[j].y, av[j].z, av[j].w};
#pragma unroll
            for (int c = 0; c < 4; c++) {
                int ln = r8 * 4 + c, reg = khalf * 2 + rbit;
                base[((kstep * 8 + mt) * 32 + ln) * 4 + reg] = v[c];
            }
        }
        float* bb = base + 4096;
#pragma unroll
        for (int j = 0; j < 2; j++) {               // scatter B into fragment layout
            int f4 = tid + j * NTHR, e = f4 >> 3, k4 = f4 & 7;
            int nt = e >> 3, n8 = e & 7;
            int kstep = k4 >> 1, khalf = k4 & 1;
            float v[4] = {bv[j].x, bv[j].y, bv[j].z, bv[j].w};
#pragma unroll
            for (int c = 0; c < 4; c++)
                bb[((kstep * 8 + nt) * 32 + n8 * 4 + c) * 2 + khalf] = v[c];
        }
    };

    auto COMP = [&](int s) {
        const float* base = sf + s * STAGE_F;
        const float* bb   = base + 4096;
#pragma unroll
        for (int ks = 0; ks < 4; ks++) {
            uint32_t ah[2][4], al[2][4];
#pragma unroll
            for (int mt = 0; mt < 2; mt++) {
                float4 a = *(const float4*)(base + ((ks * 8 + wm * 2 + mt) * 32 + lane) * 4);
                float af[4] = {a.x, a.y, a.z, a.w};
#pragma unroll
                for (int q = 0; q < 4; q++) {
                    uint32_t h = f2tf(af[q]);
                    float lo = af[q] - __uint_as_float(h);   // exact residual
                    ah[mt][q] = h;
                    al[mt][q] = f2tf(lo);
                }
            }
#pragma unroll
            for (int nt = 0; nt < 4; nt++) {
                float2 b = *(const float2*)(bb + ((ks * 8 + wn * 4 + nt) * 32 + lane) * 2);
                uint32_t bh[2], bl[2];
                float bf[2] = {b.x, b.y};
#pragma unroll
                for (int q = 0; q < 2; q++) {
                    uint32_t h = f2tf(bf[q]);
                    float lo = bf[q] - __uint_as_float(h);
                    bh[q] = h;
                    bl[q] = f2tf(lo);
                }
#pragma unroll
                for (int mt = 0; mt < 2; mt++) {
                    mma8(acc[mt][nt], ah[mt], bh);   // hi*hi
                    mma8(acc[mt][nt], ah[mt], bl);   // hi*lo
                    mma8(acc[mt][nt], al[mt], bh);   // lo*hi
                }
            }
        }
    };

    // ---- software pipeline (double buffered) ----
    LDGT(0);
    STST(0);
    LDGT(1);
    __syncthreads();

#pragma unroll 1
    for (int i = 0; i < NKIT; i++) {
        int s = i & 1;
        COMP(s);
        if (i + 1 < NKIT) {
            __syncthreads();          // everyone done reading stage s^1 (iter i-1)
            STST(s ^ 1);              // write tile i+1
            if (i + 2 < NKIT) LDGT(i + 2);
            __syncthreads();          // stage s^1 ready
        }
    }
    __syncthreads();

    // ---- epilogue: accumulators -> smem logits[128][65] -> per-token top-2 ----
    float* lg = sf;   // overlay (8320 floats <= 12288)
#pragma unroll
    for (int mt = 0; mt < 2; mt++)
#pragma unroll
        for (int nt = 0; nt < 4; nt++) {
            int r0 = wm * 32 + mt * 16 + (lane >> 2);
            int c0 = wn * 32 + nt * 8 + (lane & 3) * 2;
            lg[r0 * 65 + c0]           = acc[mt][nt][0];
            lg[r0 * 65 + c0 + 1]       = acc[mt][nt][1];
            lg[(r0 + 8) * 65 + c0]     = acc[mt][nt][2];
            lg[(r0 + 8) * 65 + c0 + 1] = acc[mt][nt][3];
        }
    __syncthreads();

    if (tid < BM) {
        const float* row = lg + tid * 65;
        float b1 = -INFINITY, b2 = -INFINITY;
        int i1 = 0, i2 = 0;
#pragma unroll 8
        for (int e = 0; e < NEXP; e++) {
            float v = row[e];
            if (v > b1)      { b2 = b1; i2 = i1; b1 = v; i1 = e; }
            else if (v > b2) { b2 = v; i2 = e; }
        }
        float e2    = expf(b2 - b1);
        float denom = 1.0f + e2;
        int t = tok0 + tid;
        g_prob[2 * t]     = 1.0f / denom;
        g_prob[2 * t + 1] = e2 / denom;
        g_idx[2 * t]      = i1;
        g_idx[2 * t + 1]  = i2;
        atomicAdd(&g_cnt[i1], 1);
        atomicAdd(&g_cnt[i2], 1);
    }
}

// ---------------- capacity enforcement + output assembly ----------------
// Output layout (float32): [ final_probs 32768 | final_indices 32768 | counts 64 ]
__global__ void finalize_kernel(float* __restrict__ out, int out_size) {
    int i = blockIdx.x * blockDim.x + threadIdx.x;
    const int NPAIR = 2 * N_TOKENS;
    if (i < NPAIR) {
        int t = i >> 1;
        int e = g_idx[i];
        float p = g_prob[i];
        bool drop = false;
        if (g_cnt[e] > CAPACITY) {
            int rank = 0;
            for (int j = 0; j < NPAIR; j++) {
                if (g_idx[j] == e) {
                    float q = g_prob[j];
                    if (q > p || (q == p && (j >> 1) < t)) rank++;
                }
            }
            drop = (rank >= CAPACITY);
        }
        out[i] = drop ? 0.0f : p;
        if (out_size >= 2 * NPAIR)
            out[NPAIR + i] = drop ? 2147483648.0f /* float(INT32_MAX) */ : (float)e;
    } else if (i < NPAIR + NEXP) {
        int e = i - NPAIR;
        if (out_size >= 2 * NPAIR + NEXP)
            out[2 * NPAIR + e] = (float)g_cnt[e];
    }
}

// ---------------- launch ----------------
extern "C" void kernel_launch(void* const* d_in, const int* in_sizes, int n_in,
                              void* d_out, int out_size) {
    const float* x = (const float*)d_in[0];
    const float* W = (const float*)d_in[1];
    if (n_in >= 2 && in_sizes[0] < in_sizes[1]) { const float* t = x; x = W; W = t; }
    float* out = (float*)d_out;

    zero_counts_kernel<<<1, 64>>>();
    gemm_route_kernel<<<N_TOKENS / BM, NTHR>>>(x, W);
    int nfin = 2 * N_TOKENS + NEXP;
    finalize_kernel<<<(nfin + 255) / 256, 256>>>(out, out_size);
}